// round 1
// baseline (speedup 1.0000x reference)
#include <cuda_runtime.h>
#include <cstdint>

// Q4_0 dequant-GEMM baseline: out[M,N] = x[M,K] * W[N,K]^T + bias
// W row o, block b (32 weights): 16 bytes (stored as int32 each), low nibble ->
// elems 0..15, high nibble -> 16..31, w = (nibble - 8) * scale[o,b].

#define BM 128
#define BN 128
#define BK 32   // == Q4_0 block size: one scale per (o, k-tile)
#define TM 8
#define TN 8
#define NTHREADS 256

__global__ __launch_bounds__(NTHREADS, 2)
void q4_gemm_kernel(const float* __restrict__ x,
                    const int*   __restrict__ qw,
                    const float* __restrict__ scales,
                    const float* __restrict__ bias,
                    float* __restrict__ out,
                    int M, int N, int K, int NB)
{
    __shared__ float Xs[BK][BM + 4];
    __shared__ float Ws[BK][BN + 4];

    const int tid = threadIdx.x;
    const int bm  = blockIdx.y * BM;
    const int bn  = blockIdx.x * BN;

    const int tx = tid & 15;        // 0..15  -> n direction
    const int ty = tid >> 4;        // 0..15  -> m direction
    const int m0 = ty * TM;
    const int n0 = tx * TN;

    float acc[TM][TN];
    #pragma unroll
    for (int i = 0; i < TM; ++i)
        #pragma unroll
        for (int j = 0; j < TN; ++j)
            acc[i][j] = 0.0f;

    const int nTiles = K / BK;
    for (int kt = 0; kt < nTiles; ++kt) {
        // ---- load X tile [BM x BK] fp32, store transposed Xs[k][m] ----
        // 128 rows * 8 float4/row = 1024 float4 ; 256 threads -> 4 each
        #pragma unroll
        for (int i = 0; i < 4; ++i) {
            int l   = tid + i * NTHREADS;
            int row = l >> 3;          // 0..127
            int c4  = l & 7;           // 0..7
            float4 v = *(const float4*)&x[(size_t)(bm + row) * K + (size_t)kt * BK + c4 * 4];
            Xs[c4 * 4 + 0][row] = v.x;
            Xs[c4 * 4 + 1][row] = v.y;
            Xs[c4 * 4 + 2][row] = v.z;
            Xs[c4 * 4 + 3][row] = v.w;
        }

        // ---- load + dequant W tile: 128 output rows, block index b = kt ----
        // 2 threads per output row; each handles 8 bytes -> 16 weights.
        {
            int r    = tid >> 1;               // 0..127 (row within tile)
            int half = tid & 1;                // byte group 0..7 or 8..15
            int o    = bn + r;
            const int* q = &qw[(((size_t)o * NB) + kt) * 16 + half * 8];
            float s = scales[(size_t)o * NB + kt];
            int4 q0 = *(const int4*)&q[0];
            int4 q1 = *(const int4*)&q[4];
            int vals[8] = {q0.x, q0.y, q0.z, q0.w, q1.x, q1.y, q1.z, q1.w};
            #pragma unroll
            for (int i = 0; i < 8; ++i) {
                int byte = vals[i];
                int j    = half * 8 + i;                     // 0..15
                Ws[j     ][r] = s * (float)((byte        & 0xF) - 8);
                Ws[j + 16][r] = s * (float)(((byte >> 4) & 0xF) - 8);
            }
        }

        __syncthreads();

        // ---- compute: 8x8 per-thread micro-tile over k = 0..31 ----
        #pragma unroll
        for (int k = 0; k < BK; ++k) {
            float a[TM], b[TN];
            *(float4*)&a[0] = *(const float4*)&Xs[k][m0];
            *(float4*)&a[4] = *(const float4*)&Xs[k][m0 + 4];
            *(float4*)&b[0] = *(const float4*)&Ws[k][n0];
            *(float4*)&b[4] = *(const float4*)&Ws[k][n0 + 4];
            #pragma unroll
            for (int i = 0; i < TM; ++i)
                #pragma unroll
                for (int j = 0; j < TN; ++j)
                    acc[i][j] += a[i] * b[j];
        }

        __syncthreads();
    }

    // ---- epilogue: add bias, write out ----
    #pragma unroll
    for (int i = 0; i < TM; ++i) {
        int m = bm + m0 + i;
        #pragma unroll
        for (int j = 0; j < TN; j += 4) {
            int n = bn + n0 + j;
            float4 r;
            r.x = acc[i][j + 0] + bias[n + 0];
            r.y = acc[i][j + 1] + bias[n + 1];
            r.z = acc[i][j + 2] + bias[n + 2];
            r.w = acc[i][j + 3] + bias[n + 3];
            *(float4*)&out[(size_t)m * N + n] = r;
        }
    }
}

extern "C" void kernel_launch(void* const* d_in, const int* in_sizes, int n_in,
                              void* d_out, int out_size)
{
    const float* x      = (const float*)d_in[0];
    const int*   qw     = (const int*)  d_in[1];
    const float* scales = (const float*)d_in[2];
    const float* bias   = (const float*)d_in[3];
    float*       out    = (float*)d_out;

    const int O  = in_sizes[3];            // 8192
    const int NB = in_sizes[2] / O;        // 256
    const int K  = NB * 32;                // 8192
    const int M  = in_sizes[0] / K;        // 4096
    const int N  = O;

    dim3 block(NTHREADS);
    dim3 grid(N / BN, M / BM);
    q4_gemm_kernel<<<grid, block>>>(x, qw, scales, bias, out, M, N, K, NB);
}

// round 4
// speedup vs baseline: 4.6706x; 4.6706x over previous
#include <cuda_runtime.h>
#include <cuda_fp16.h>
#include <cstdint>

// Q4_0 dequant GEMM via legacy mma.sync (HMMA) fp16, fp32 accum.
// out[M,N] = x[M,K] * W[N,K]^T + bias,  W = (nib-8)*scale per 32-k block.
// NOTE: harness targets sm_103 (base) — tcgen05/WGMMA unavailable; mma.sync it is.

#define BM 128
#define BN 256
#define BK 32
#define NTH 256
#define ROWB 80                      // 16B-aligned row stride; (5r+c)%8 distinct -> no ldsm conflicts
#define A_BYTES (128 * ROWB)         // 10240
#define B_BYTES (256 * ROWB)         // 20480
#define STAGE_BYTES (A_BYTES + B_BYTES)
#define NSTAGE 3
#define SMEM_BYTES (NSTAGE * STAGE_BYTES)

__device__ __forceinline__ uint32_t smem_u32(const void* p) {
    uint32_t a;
    asm("{ .reg .u64 t; cvta.to.shared.u64 t, %1; cvt.u32.u64 %0, t; }" : "=r"(a) : "l"(p));
    return a;
}

__device__ __forceinline__ void ldsm4(uint32_t r[4], uint32_t addr) {
    asm volatile("ldmatrix.sync.aligned.m8n8.x4.shared.b16 {%0,%1,%2,%3}, [%4];"
                 : "=r"(r[0]), "=r"(r[1]), "=r"(r[2]), "=r"(r[3]) : "r"(addr));
}

__device__ __forceinline__ void mma16816(float c[4], const uint32_t a[4],
                                         uint32_t b0, uint32_t b1) {
    asm volatile("mma.sync.aligned.m16n8k16.row.col.f32.f16.f16.f32 "
                 "{%0,%1,%2,%3}, {%4,%5,%6,%7}, {%8,%9}, {%0,%1,%2,%3};"
                 : "+f"(c[0]), "+f"(c[1]), "+f"(c[2]), "+f"(c[3])
                 : "r"(a[0]), "r"(a[1]), "r"(a[2]), "r"(a[3]), "r"(b0), "r"(b1));
}

__device__ __forceinline__ void sts64(uint32_t addr, uint32_t a, uint32_t b) {
    asm volatile("st.shared.v2.b32 [%0], {%1,%2};" :: "r"(addr), "r"(a), "r"(b));
}
__device__ __forceinline__ void sts128(uint32_t addr, uint32_t a, uint32_t b,
                                       uint32_t c, uint32_t d) {
    asm volatile("st.shared.v4.b32 [%0], {%1,%2,%3,%4};"
                 :: "r"(addr), "r"(a), "r"(b), "r"(c), "r"(d));
}

__device__ __forceinline__ uint32_t h2u(__half2 h) { return *reinterpret_cast<uint32_t*>(&h); }
__device__ __forceinline__ __half2 u2h(uint32_t u) { return *reinterpret_cast<__half2*>(&u); }

__global__ __launch_bounds__(NTH, 1)
void q4_hmma_kernel(const float* __restrict__ x,
                    const int*   __restrict__ qw,
                    const float* __restrict__ scales,
                    const float* __restrict__ bias,
                    float* __restrict__ out,
                    int M, int N, int K, int NB)
{
    extern __shared__ __align__(128) char smem[];
    const uint32_t sbase = smem_u32(smem);

    const int tid  = threadIdx.x;
    const int lane = tid & 31;
    const int wid  = tid >> 5;
    const int bm   = blockIdx.y * BM;
    const int bn   = blockIdx.x * BN;
    const int NT   = K / BK;   // 256

    const int m_off = (wid & 1) * 64;
    const int n_off = (wid >> 1) * 64;

    // per-lane ldmatrix base offsets (relative to A-/B-region base of a stage)
    const uint32_t aLd = (uint32_t)((m_off + (lane & 15)) * ROWB + (lane >> 4) * 16);
    const uint32_t bLd = (uint32_t)((n_off + (lane & 7) + ((lane & 16) ? 8 : 0)) * ROWB
                                    + ((lane >> 3) & 1) * 16);

    float acc[4][8][4];
    #pragma unroll
    for (int i = 0; i < 4; ++i)
        #pragma unroll
        for (int j = 0; j < 8; ++j)
            #pragma unroll
            for (int v = 0; v < 4; ++v) acc[i][j][v] = 0.0f;

    // producer setup: B row r = tid (one Q4 row per thread)
    const int r = tid;
    const int4*  qbase = (const int4*)(qw + ((size_t)(bn + r) * NB) * 16);
    const float* scbase = scales + (size_t)(bn + r) * NB;
    const uint32_t c1032 = 0x64086408u;                       // half2(1032,1032)

    float4 sc4 = *(const float4*)&scbase[0];
    float4 av[4];
    int4   bv[4];

    // ---- helpers as macros over locals ----
#define LOADG(KT)                                                                       \
    do {                                                                                \
        _Pragma("unroll")                                                               \
        for (int i = 0; i < 4; ++i) {                                                   \
            int idx = tid + i * NTH, row = idx >> 3, ch = idx & 7;                      \
            av[i] = *(const float4*)&x[(size_t)(bm + row) * K + (KT) * BK + ch * 4];    \
        }                                                                               \
        _Pragma("unroll")                                                               \
        for (int i = 0; i < 4; ++i) bv[i] = qbase[(KT) * 4 + i];                        \
    } while (0)

#define STORE(KT)                                                                       \
    do {                                                                                \
        const uint32_t st = sbase + ((KT) % NSTAGE) * STAGE_BYTES;                      \
        _Pragma("unroll")                                                               \
        for (int i = 0; i < 4; ++i) {                                                   \
            int idx = tid + i * NTH, row = idx >> 3, ch = idx & 7;                      \
            __half2 h0 = __floats2half2_rn(av[i].x, av[i].y);                           \
            __half2 h1 = __floats2half2_rn(av[i].z, av[i].w);                           \
            sts64(st + (uint32_t)(row * ROWB + ch * 8), h2u(h0), h2u(h1));              \
        }                                                                               \
        int kb = (KT) & 3;                                                              \
        float s = (kb & 1) ? ((kb & 2) ? sc4.w : sc4.y) : ((kb & 2) ? sc4.z : sc4.x);   \
        __half2 s2 = __half2half2(__float2half_rn(s));                                  \
        int q[16];                                                                      \
        q[0]=bv[0].x; q[1]=bv[0].y; q[2]=bv[0].z; q[3]=bv[0].w;                         \
        q[4]=bv[1].x; q[5]=bv[1].y; q[6]=bv[1].z; q[7]=bv[1].w;                         \
        q[8]=bv[2].x; q[9]=bv[2].y; q[10]=bv[2].z; q[11]=bv[2].w;                       \
        q[12]=bv[3].x; q[13]=bv[3].y; q[14]=bv[3].z; q[15]=bv[3].w;                     \
        uint32_t w[16];                                                                 \
        _Pragma("unroll")                                                               \
        for (int j = 0; j < 8; ++j) {                                                   \
            int q0 = q[2*j], q1 = q[2*j+1];                                             \
            uint32_t lo = (uint32_t)(q0 & 0xF) | (((uint32_t)(q1 & 0xF)) << 16)         \
                          | 0x64006400u;                                                \
            uint32_t hi = (uint32_t)((q0 >> 4) & 0xF)                                   \
                          | (((uint32_t)((q1 >> 4) & 0xF)) << 16) | 0x64006400u;        \
            w[j]     = h2u(__hmul2(__hsub2(u2h(lo), u2h(c1032)), s2));                  \
            w[8 + j] = h2u(__hmul2(__hsub2(u2h(hi), u2h(c1032)), s2));                  \
        }                                                                               \
        uint32_t bst = st + A_BYTES + (uint32_t)(r * ROWB);                             \
        sts128(bst +  0, w[0],  w[1],  w[2],  w[3]);                                    \
        sts128(bst + 16, w[4],  w[5],  w[6],  w[7]);                                    \
        sts128(bst + 32, w[8],  w[9],  w[10], w[11]);                                   \
        sts128(bst + 48, w[12], w[13], w[14], w[15]);                                   \
    } while (0)

    // prologue: fill stage 0
    LOADG(0);
    STORE(0);

    for (int kt = 0; kt < NT; ++kt) {
        __syncthreads();

        const int kn = kt + 1;
        if (kn < NT) {
            if ((kn & 3) == 0) sc4 = *(const float4*)&scbase[kn];
            LOADG(kn);
        }

        // ---- MMA on stage kt%3 ----
        {
            const uint32_t st = sbase + (kt % NSTAGE) * STAGE_BYTES;
            const uint32_t aB = st + aLd;
            const uint32_t bB = st + A_BYTES + bLd;
            #pragma unroll
            for (int ks = 0; ks < 2; ++ks) {
                uint32_t a[4][4];
                #pragma unroll
                for (int mf = 0; mf < 4; ++mf)
                    ldsm4(a[mf], aB + (uint32_t)(mf * 16 * ROWB + ks * 32));
                uint32_t b[4][4];
                #pragma unroll
                for (int np = 0; np < 4; ++np)
                    ldsm4(b[np], bB + (uint32_t)(np * 16 * ROWB + ks * 32));
                #pragma unroll
                for (int mf = 0; mf < 4; ++mf)
                    #pragma unroll
                    for (int nf = 0; nf < 8; ++nf)
                        mma16816(acc[mf][nf], a[mf], b[nf >> 1][(nf & 1) * 2],
                                 b[nf >> 1][(nf & 1) * 2 + 1]);
            }
        }

        if (kn < NT) STORE(kn);
    }

    // ---- epilogue: bias + store ----
    {
        const int g = lane >> 2, t = lane & 3;
        #pragma unroll
        for (int nf = 0; nf < 8; ++nf) {
            const int col = bn + n_off + nf * 8 + 2 * t;
            const float2 bb = *(const float2*)&bias[col];
            #pragma unroll
            for (int mf = 0; mf < 4; ++mf) {
                const int row = bm + m_off + mf * 16 + g;
                float2 o0, o1;
                o0.x = acc[mf][nf][0] + bb.x;
                o0.y = acc[mf][nf][1] + bb.y;
                o1.x = acc[mf][nf][2] + bb.x;
                o1.y = acc[mf][nf][3] + bb.y;
                *(float2*)&out[(size_t)row * N + col]       = o0;
                *(float2*)&out[(size_t)(row + 8) * N + col] = o1;
            }
        }
    }
}

extern "C" void kernel_launch(void* const* d_in, const int* in_sizes, int n_in,
                              void* d_out, int out_size)
{
    const float* x      = (const float*)d_in[0];
    const int*   qw     = (const int*)  d_in[1];
    const float* scales = (const float*)d_in[2];
    const float* bias   = (const float*)d_in[3];
    float*       out    = (float*)d_out;

    const int O  = in_sizes[3];            // 8192
    const int NB = in_sizes[2] / O;        // 256
    const int K  = NB * 32;                // 8192
    const int M  = in_sizes[0] / K;        // 4096
    const int N  = O;

    cudaFuncSetAttribute(q4_hmma_kernel, cudaFuncAttributeMaxDynamicSharedMemorySize,
                         SMEM_BYTES);

    dim3 grid(N / BN, M / BM);
    q4_hmma_kernel<<<grid, NTH, SMEM_BYTES>>>(x, qw, scales, bias, out, M, N, K, NB);
}

// round 5
// speedup vs baseline: 5.0904x; 1.0899x over previous
#include <cuda_runtime.h>
#include <cuda_fp16.h>
#include <cstdint>

// Q4_0 dequant GEMM via mma.sync (HMMA) fp16, fp32 accum.
// Round 5: CTA tile 128x128, warp tile 64x32, __launch_bounds__(256,2)
// -> 2 CTAs/SM (16 warps) to hide ldsm/barrier latency and fill tensor pipe.

#define BM 128
#define BN 128
#define BK 32
#define NTH 256
#define ROWB 80                      // 16B-aligned stride; (5r+c)%8 distinct -> ldsm conflict-free
#define A_BYTES (128 * ROWB)         // 10240
#define B_BYTES (128 * ROWB)         // 10240
#define STAGE_BYTES (A_BYTES + B_BYTES)
#define NSTAGE 3
#define SMEM_BYTES (NSTAGE * STAGE_BYTES)   // 61440

__device__ __forceinline__ uint32_t smem_u32(const void* p) {
    uint32_t a;
    asm("{ .reg .u64 t; cvta.to.shared.u64 t, %1; cvt.u32.u64 %0, t; }" : "=r"(a) : "l"(p));
    return a;
}

__device__ __forceinline__ void ldsm4(uint32_t r[4], uint32_t addr) {
    asm volatile("ldmatrix.sync.aligned.m8n8.x4.shared.b16 {%0,%1,%2,%3}, [%4];"
                 : "=r"(r[0]), "=r"(r[1]), "=r"(r[2]), "=r"(r[3]) : "r"(addr));
}

__device__ __forceinline__ void mma16816(float c[4], const uint32_t a[4],
                                         uint32_t b0, uint32_t b1) {
    asm volatile("mma.sync.aligned.m16n8k16.row.col.f32.f16.f16.f32 "
                 "{%0,%1,%2,%3}, {%4,%5,%6,%7}, {%8,%9}, {%0,%1,%2,%3};"
                 : "+f"(c[0]), "+f"(c[1]), "+f"(c[2]), "+f"(c[3])
                 : "r"(a[0]), "r"(a[1]), "r"(a[2]), "r"(a[3]), "r"(b0), "r"(b1));
}

__device__ __forceinline__ void sts64(uint32_t addr, uint32_t a, uint32_t b) {
    asm volatile("st.shared.v2.b32 [%0], {%1,%2};" :: "r"(addr), "r"(a), "r"(b));
}
__device__ __forceinline__ void sts128(uint32_t addr, uint32_t a, uint32_t b,
                                       uint32_t c, uint32_t d) {
    asm volatile("st.shared.v4.b32 [%0], {%1,%2,%3,%4};"
                 :: "r"(addr), "r"(a), "r"(b), "r"(c), "r"(d));
}

__device__ __forceinline__ uint32_t h2u(__half2 h) { return *reinterpret_cast<uint32_t*>(&h); }
__device__ __forceinline__ __half2 u2h(uint32_t u) { return *reinterpret_cast<__half2*>(&u); }

__global__ __launch_bounds__(NTH, 2)
void q4_hmma_kernel(const float* __restrict__ x,
                    const int*   __restrict__ qw,
                    const float* __restrict__ scales,
                    const float* __restrict__ bias,
                    float* __restrict__ out,
                    int M, int N, int K, int NB)
{
    extern __shared__ __align__(128) char smem[];
    const uint32_t sbase = smem_u32(smem);

    const int tid  = threadIdx.x;
    const int lane = tid & 31;
    const int wid  = tid >> 5;
    const int bm   = blockIdx.y * BM;
    const int bn   = blockIdx.x * BN;
    const int NT   = K / BK;   // 256

    // 8 warps: 2 (m) x 4 (n); warp tile 64x32
    const int m_off = (wid & 1) * 64;
    const int n_off = (wid >> 1) * 32;

    const uint32_t aLd = (uint32_t)((m_off + (lane & 15)) * ROWB + (lane >> 4) * 16);
    const uint32_t bLd = (uint32_t)((n_off + (lane & 7) + ((lane & 16) ? 8 : 0)) * ROWB
                                    + ((lane >> 3) & 1) * 16);

    float acc[4][4][4];
    #pragma unroll
    for (int i = 0; i < 4; ++i)
        #pragma unroll
        for (int j = 0; j < 4; ++j)
            #pragma unroll
            for (int v = 0; v < 4; ++v) acc[i][j][v] = 0.0f;

    // producer B: row r = tid>>1, byte-half = tid&1 (8 packed bytes = 8 int32)
    const int rB   = tid >> 1;
    const int half = tid & 1;
    const int4*  qbase  = (const int4*)(qw + (((size_t)(bn + rB) * NB) * 16)) + half * 2;
    const float* scbase = scales + (size_t)(bn + rB) * NB;
    const uint32_t c1032 = 0x64086408u;                       // half2(1032,1032)

    float4 sc4 = *(const float4*)&scbase[0];
    float4 av[4];
    int4   bv[2];

#define LOADG(KT)                                                                       \
    do {                                                                                \
        _Pragma("unroll")                                                               \
        for (int i = 0; i < 4; ++i) {                                                   \
            int idx = tid + i * NTH, row = idx >> 3, ch = idx & 7;                      \
            av[i] = *(const float4*)&x[(size_t)(bm + row) * K + (KT) * BK + ch * 4];    \
        }                                                                               \
        bv[0] = qbase[(KT) * 4 + 0];                                                    \
        bv[1] = qbase[(KT) * 4 + 1];                                                    \
    } while (0)

#define STORE(KT)                                                                       \
    do {                                                                                \
        const uint32_t st = sbase + ((KT) % NSTAGE) * STAGE_BYTES;                      \
        _Pragma("unroll")                                                               \
        for (int i = 0; i < 4; ++i) {                                                   \
            int idx = tid + i * NTH, row = idx >> 3, ch = idx & 7;                      \
            __half2 h0 = __floats2half2_rn(av[i].x, av[i].y);                           \
            __half2 h1 = __floats2half2_rn(av[i].z, av[i].w);                           \
            sts64(st + (uint32_t)(row * ROWB + ch * 8), h2u(h0), h2u(h1));              \
        }                                                                               \
        int kb = (KT) & 3;                                                              \
        float s = (kb & 1) ? ((kb & 2) ? sc4.w : sc4.y) : ((kb & 2) ? sc4.z : sc4.x);   \
        __half2 s2 = __half2half2(__float2half_rn(s));                                  \
        int q[8];                                                                       \
        q[0]=bv[0].x; q[1]=bv[0].y; q[2]=bv[0].z; q[3]=bv[0].w;                         \
        q[4]=bv[1].x; q[5]=bv[1].y; q[6]=bv[1].z; q[7]=bv[1].w;                         \
        uint32_t w[8];                                                                  \
        _Pragma("unroll")                                                               \
        for (int j = 0; j < 4; ++j) {                                                   \
            int q0 = q[2*j], q1 = q[2*j+1];                                             \
            uint32_t lo = (uint32_t)(q0 & 0xF) | (((uint32_t)(q1 & 0xF)) << 16)         \
                          | 0x64006400u;                                                \
            uint32_t hi = (uint32_t)((q0 >> 4) & 0xF)                                   \
                          | (((uint32_t)((q1 >> 4) & 0xF)) << 16) | 0x64006400u;        \
            w[j]     = h2u(__hmul2(__hsub2(u2h(lo), u2h(c1032)), s2));                  \
            w[4 + j] = h2u(__hmul2(__hsub2(u2h(hi), u2h(c1032)), s2));                  \
        }                                                                               \
        uint32_t bst = st + A_BYTES + (uint32_t)(rB * ROWB + half * 16);                \
        sts128(bst +  0, w[0], w[1], w[2], w[3]);                                       \
        sts128(bst + 32, w[4], w[5], w[6], w[7]);                                       \
    } while (0)

    // prologue
    LOADG(0);
    STORE(0);

    for (int kt = 0; kt < NT; ++kt) {
        __syncthreads();

        const int kn = kt + 1;
        if (kn < NT) {
            if ((kn & 3) == 0) sc4 = *(const float4*)&scbase[kn];
            LOADG(kn);
        }

        // ---- MMA on stage kt%3 ----
        {
            const uint32_t st = sbase + (kt % NSTAGE) * STAGE_BYTES;
            const uint32_t aB = st + aLd;
            const uint32_t bB = st + A_BYTES + bLd;
            #pragma unroll
            for (int ks = 0; ks < 2; ++ks) {
                uint32_t a[4][4];
                #pragma unroll
                for (int mf = 0; mf < 4; ++mf)
                    ldsm4(a[mf], aB + (uint32_t)(mf * 16 * ROWB + ks * 32));
                uint32_t b[2][4];
                #pragma unroll
                for (int np = 0; np < 2; ++np)
                    ldsm4(b[np], bB + (uint32_t)(np * 16 * ROWB + ks * 32));
                #pragma unroll
                for (int mf = 0; mf < 4; ++mf)
                    #pragma unroll
                    for (int nf = 0; nf < 4; ++nf)
                        mma16816(acc[mf][nf], a[mf], b[nf >> 1][(nf & 1) * 2],
                                 b[nf >> 1][(nf & 1) * 2 + 1]);
            }
        }

        if (kn < NT) STORE(kn);
    }

    // ---- epilogue: bias + store ----
    {
        const int g = lane >> 2, t = lane & 3;
        #pragma unroll
        for (int nf = 0; nf < 4; ++nf) {
            const int col = bn + n_off + nf * 8 + 2 * t;
            const float2 bb = *(const float2*)&bias[col];
            #pragma unroll
            for (int mf = 0; mf < 4; ++mf) {
                const int row = bm + m_off + mf * 16 + g;
                float2 o0, o1;
                o0.x = acc[mf][nf][0] + bb.x;
                o0.y = acc[mf][nf][1] + bb.y;
                o1.x = acc[mf][nf][2] + bb.x;
                o1.y = acc[mf][nf][3] + bb.y;
                *(float2*)&out[(size_t)row * N + col]       = o0;
                *(float2*)&out[(size_t)(row + 8) * N + col] = o1;
            }
        }
    }
}

extern "C" void kernel_launch(void* const* d_in, const int* in_sizes, int n_in,
                              void* d_out, int out_size)
{
    const float* x      = (const float*)d_in[0];
    const int*   qw     = (const int*)  d_in[1];
    const float* scales = (const float*)d_in[2];
    const float* bias   = (const float*)d_in[3];
    float*       out    = (float*)d_out;

    const int O  = in_sizes[3];            // 8192
    const int NB = in_sizes[2] / O;        // 256
    const int K  = NB * 32;                // 8192
    const int M  = in_sizes[0] / K;        // 4096
    const int N  = O;

    cudaFuncSetAttribute(q4_hmma_kernel, cudaFuncAttributeMaxDynamicSharedMemorySize,
                         SMEM_BYTES);

    dim3 grid(N / BN, M / BM);
    q4_hmma_kernel<<<grid, NTH, SMEM_BYTES>>>(x, qw, scales, bias, out, M, N, K, NB);
}

// round 7
// speedup vs baseline: 6.7661x; 1.3292x over previous
#include <cuda_runtime.h>
#include <cuda_fp16.h>
#include <cstdint>

// Q4_0 dequant GEMM via mma.sync (HMMA) fp16, fp32 accum.
// R6: x pre-converted to fp16 (device global) -> A via cp.async;
//     CTA 128x128, 4 warps (2x2), warp tile 64x64, BK=64, 2 CTAs/SM.

#define BM 128
#define BN 128
#define BK 64
#define NTH 128
#define ROWB 144                      // 16B-aligned; (9r+c)%8 = (r+c)%8 -> ldsm conflict-free
#define A_BYTES (128 * ROWB)          // 18432
#define B_OFF   A_BYTES
#define STAGE_BYTES (2 * A_BYTES)     // 36864
#define SMEM_BYTES (2 * STAGE_BYTES)  // 73728

#define MCAP 4096
#define KCAP 8192
__device__ __half g_xh[(size_t)MCAP * KCAP];   // pre-converted x (fp16)

__device__ __forceinline__ uint32_t smem_u32(const void* p) {
    uint32_t a;
    asm("{ .reg .u64 t; cvta.to.shared.u64 t, %1; cvt.u32.u64 %0, t; }" : "=r"(a) : "l"(p));
    return a;
}
__device__ __forceinline__ void ldsm4(uint32_t r[4], uint32_t addr) {
    asm volatile("ldmatrix.sync.aligned.m8n8.x4.shared.b16 {%0,%1,%2,%3}, [%4];"
                 : "=r"(r[0]), "=r"(r[1]), "=r"(r[2]), "=r"(r[3]) : "r"(addr));
}
__device__ __forceinline__ void mma16816(float c[4], const uint32_t a[4],
                                         uint32_t b0, uint32_t b1) {
    asm volatile("mma.sync.aligned.m16n8k16.row.col.f32.f16.f16.f32 "
                 "{%0,%1,%2,%3}, {%4,%5,%6,%7}, {%8,%9}, {%0,%1,%2,%3};"
                 : "+f"(c[0]), "+f"(c[1]), "+f"(c[2]), "+f"(c[3])
                 : "r"(a[0]), "r"(a[1]), "r"(a[2]), "r"(a[3]), "r"(b0), "r"(b1));
}
__device__ __forceinline__ void sts64(uint32_t addr, uint32_t a, uint32_t b) {
    asm volatile("st.shared.v2.b32 [%0], {%1,%2};" :: "r"(addr), "r"(a), "r"(b));
}
__device__ __forceinline__ uint32_t h2u(__half2 h) { return *reinterpret_cast<uint32_t*>(&h); }
__device__ __forceinline__ __half2 u2h(uint32_t u) { return *reinterpret_cast<__half2*>(&u); }

// ---- pre-pass: fp32 x -> fp16 g_xh ----
__global__ void cvt_kernel(const float* __restrict__ x, size_t n4) {
    size_t i = (size_t)blockIdx.x * blockDim.x + threadIdx.x;
    const size_t stride = (size_t)gridDim.x * blockDim.x;
    for (; i < n4; i += stride) {
        float4 v = ((const float4*)x)[i];
        __half2 h0 = __floats2half2_rn(v.x, v.y);
        __half2 h1 = __floats2half2_rn(v.z, v.w);
        uint2 u; u.x = h2u(h0); u.y = h2u(h1);
        ((uint2*)g_xh)[i] = u;
    }
}

__global__ __launch_bounds__(NTH, 2)
void q4_hmma_kernel(const int*   __restrict__ qw,
                    const float* __restrict__ scales,
                    const float* __restrict__ bias,
                    float* __restrict__ out,
                    int M, int N, int K, int NB)
{
    extern __shared__ __align__(128) char smem[];
    const uint32_t sbase = smem_u32(smem);

    const int tid  = threadIdx.x;
    const int lane = tid & 31;
    const int wid  = tid >> 5;
    const int bm   = blockIdx.y * BM;
    const int bn   = blockIdx.x * BN;
    const int NT   = K / BK;   // 128

    // 4 warps: 2 (m) x 2 (n), warp tile 64x64
    const int m_off = (wid & 1) * 64;
    const int n_off = (wid >> 1) * 64;

    const uint32_t aLd = (uint32_t)((m_off + (lane & 15)) * ROWB + (lane >> 4) * 16);
    const uint32_t bLd = (uint32_t)((n_off + (lane & 7) + ((lane & 16) ? 8 : 0)) * ROWB
                                    + ((lane >> 3) & 1) * 16);

    float acc[4][8][4];
    #pragma unroll
    for (int i = 0; i < 4; ++i)
        #pragma unroll
        for (int j = 0; j < 8; ++j)
            #pragma unroll
            for (int v = 0; v < 4; ++v) acc[i][j][v] = 0.0f;

    const uint32_t c1032 = 0x64086408u;    // half2(1032,1032)
    int4  bv[8];
    float sc[8];

    // A tile: 128 rows x 64 fp16 = 128B/row, cp.async 16B per op, 8 ops/thread
#define CPA(KT)                                                                        \
    do {                                                                               \
        const uint32_t st = sbase + ((KT) & 1) * STAGE_BYTES;                          \
        const __half* gA = &g_xh[(size_t)bm * K + (size_t)(KT) * BK];                  \
        _Pragma("unroll")                                                              \
        for (int i = 0; i < 8; ++i) {                                                  \
            int idx = tid + i * NTH, row = idx >> 3, c = idx & 7;                      \
            uint32_t d = st + (uint32_t)(row * ROWB + c * 16);                         \
            const void* s = gA + (size_t)row * K + c * 8;                              \
            asm volatile("cp.async.cg.shared.global [%0], [%1], 16;"                   \
                         :: "r"(d), "l"(s));                                           \
        }                                                                              \
        asm volatile("cp.async.commit_group;");                                        \
    } while (0)

    // B tile: 128 rows x 2 Q4 blocks; task unit = one int4 (4 packed byte-int32s)
    // idx -> row = idx>>3, t8 = idx&7 (blk = t8>>2, c = t8&3)
#define LOADB(KT)                                                                      \
    do {                                                                               \
        _Pragma("unroll")                                                              \
        for (int i = 0; i < 8; ++i) {                                                  \
            int idx = tid + i * NTH, row = idx >> 3, t8 = idx & 7;                     \
            const int* qb = qw + ((size_t)(bn + row) * NB + (KT) * 2) * 16 + t8 * 4;   \
            bv[i] = *(const int4*)qb;                                                  \
            sc[i] = __ldg(&scales[(size_t)(bn + row) * NB + (KT) * 2 + (t8 >> 2)]);    \
        }                                                                              \
    } while (0)

#define STOREB(KT)                                                                     \
    do {                                                                               \
        const uint32_t st = sbase + ((KT) & 1) * STAGE_BYTES;                          \
        _Pragma("unroll")                                                              \
        for (int i = 0; i < 8; ++i) {                                                  \
            int idx = tid + i * NTH, row = idx >> 3, t8 = idx & 7;                     \
            int blk = t8 >> 2, c = t8 & 3;                                             \
            __half2 s2 = __half2half2(__float2half_rn(sc[i]));                         \
            int q0 = bv[i].x, q1 = bv[i].y, q2 = bv[i].z, q3 = bv[i].w;                \
            uint32_t lo0 = (uint32_t)(q0 & 0xF) | (((uint32_t)(q1 & 0xF)) << 16)       \
                           | 0x64006400u;                                              \
            uint32_t lo1 = (uint32_t)(q2 & 0xF) | (((uint32_t)(q3 & 0xF)) << 16)       \
                           | 0x64006400u;                                              \
            uint32_t hi0 = (uint32_t)((q0 >> 4) & 0xF)                                 \
                           | (((uint32_t)((q1 >> 4) & 0xF)) << 16) | 0x64006400u;      \
            uint32_t hi1 = (uint32_t)((q2 >> 4) & 0xF)                                 \
                           | (((uint32_t)((q3 >> 4) & 0xF)) << 16) | 0x64006400u;      \
            uint32_t wl0 = h2u(__hmul2(__hsub2(u2h(lo0), u2h(c1032)), s2));            \
            uint32_t wl1 = h2u(__hmul2(__hsub2(u2h(lo1), u2h(c1032)), s2));            \
            uint32_t wh0 = h2u(__hmul2(__hsub2(u2h(hi0), u2h(c1032)), s2));            \
            uint32_t wh1 = h2u(__hmul2(__hsub2(u2h(hi1), u2h(c1032)), s2));            \
            uint32_t dst = st + B_OFF + (uint32_t)(row * ROWB + blk * 64 + c * 8);     \
            sts64(dst,      wl0, wl1);                                                 \
            sts64(dst + 32, wh0, wh1);                                                 \
        }                                                                              \
    } while (0)

    // prologue: stage 0
    LOADB(0);
    STOREB(0);
    CPA(0);

    for (int kt = 0; kt < NT; ++kt) {
        const int kn = kt + 1;
        if (kn < NT) LOADB(kn);

        // my cp.async group for stage kt must have landed...
        asm volatile("cp.async.wait_group 0;" ::: "memory");
        // ...and everyone's (plus B STS of kt) visible after the barrier
        __syncthreads();

        if (kn < NT) CPA(kn);   // write A stage kn&1 (MMA(kt-1) on it finished pre-sync)

        // ---- MMA on stage kt ----
        {
            const uint32_t st = sbase + (kt & 1) * STAGE_BYTES;
            const uint32_t aB = st + aLd;
            const uint32_t bB = st + B_OFF + bLd;
            #pragma unroll
            for (int ks = 0; ks < 4; ++ks) {
                uint32_t a[4][4];
                #pragma unroll
                for (int mf = 0; mf < 4; ++mf)
                    ldsm4(a[mf], aB + (uint32_t)(mf * 16 * ROWB + ks * 32));
                uint32_t b[4][4];
                #pragma unroll
                for (int np = 0; np < 4; ++np)
                    ldsm4(b[np], bB + (uint32_t)(np * 16 * ROWB + ks * 32));
                #pragma unroll
                for (int mf = 0; mf < 4; ++mf)
                    #pragma unroll
                    for (int nf = 0; nf < 8; ++nf)
                        mma16816(acc[mf][nf], a[mf], b[nf >> 1][(nf & 1) * 2],
                                 b[nf >> 1][(nf & 1) * 2 + 1]);
            }
        }

        if (kn < NT) STOREB(kn);
    }

    // ---- epilogue: bias + store ----
    {
        const int g = lane >> 2, t = lane & 3;
        #pragma unroll
        for (int nf = 0; nf < 8; ++nf) {
            const int col = bn + n_off + nf * 8 + 2 * t;
            const float2 bb = *(const float2*)&bias[col];
            #pragma unroll
            for (int mf = 0; mf < 4; ++mf) {
                const int row = bm + m_off + mf * 16 + g;
                float2 o0, o1;
                o0.x = acc[mf][nf][0] + bb.x;
                o0.y = acc[mf][nf][1] + bb.y;
                o1.x = acc[mf][nf][2] + bb.x;
                o1.y = acc[mf][nf][3] + bb.y;
                *(float2*)&out[(size_t)row * N + col]       = o0;
                *(float2*)&out[(size_t)(row + 8) * N + col] = o1;
            }
        }
    }
}

extern "C" void kernel_launch(void* const* d_in, const int* in_sizes, int n_in,
                              void* d_out, int out_size)
{
    const float* x      = (const float*)d_in[0];
    const int*   qw     = (const int*)  d_in[1];
    const float* scales = (const float*)d_in[2];
    const float* bias   = (const float*)d_in[3];
    float*       out    = (float*)d_out;

    const int O  = in_sizes[3];            // 8192
    const int NB = in_sizes[2] / O;        // 256
    const int K  = NB * 32;                // 8192
    const int M  = in_sizes[0] / K;        // 4096
    const int N  = O;

    // pre-pass: x -> fp16
    cvt_kernel<<<1024, 256>>>(x, (size_t)M * K / 4);

    cudaFuncSetAttribute(q4_hmma_kernel, cudaFuncAttributeMaxDynamicSharedMemorySize,
                         SMEM_BYTES);
    dim3 grid(N / BN, M / BM);
    q4_hmma_kernel<<<grid, NTH, SMEM_BYTES>>>(qw, scales, bias, out, M, N, K, NB);
}